// round 13
// baseline (speedup 1.0000x reference)
#include <cuda_runtime.h>
#include <cstdint>

typedef unsigned long long ull;

#define NCTA      4
#define HID       128
#define NTHREADS  1024
#define NWIN      252
#define TT        256
#define PADW      132     // weight row stride (floats)
#define HB        160     // per-batch h stride: 8 chunks of (16 data + 4 pad)

// row layout: lr = wid*4 + g   (warp wid = unit, g = gate 0..3, PyTorch i,f,g,o)
struct Smem {
    float W1s[128 * PADW];   // Wih1
    float U1s[128 * PADW];   // Whh1
    float U0s[128 * PADW];   // Whh0
    float W0s[128 * 4];      // Wih0 (3 cols + pad)
    float b0s[128];
    float b1s[128];
    float h0buf[2][4 * HB];  // ping-pong, cluster-shared, chunk-padded
    float h1buf[2][4 * HB];
    float xin[4 * 4 * 4];    // [t][b][f pad4]
    float Wl[2 * HID];
    float winbuf[4 * 4 * 2]; // ring: [b][slot][o], pred of window p at slot p&3
    float pred[4 * 2];
    float bl[2];
};

#define FFMA2(acc, w, h) \
    asm("fma.rn.f32x2 %0, %1, %2, %0;" : "+l"(acc) : "l"(w), "l"(h))

__device__ __forceinline__ float hsum2(ull a) {
    float lo, hi;
    asm("mov.b64 {%0, %1}, %2;" : "=f"(lo), "=f"(hi) : "l"(a));
    return lo + hi;
}

__device__ __forceinline__ void cluster_sync_all() {
    asm volatile("barrier.cluster.arrive.aligned;" ::: "memory");
    asm volatile("barrier.cluster.wait.aligned;" ::: "memory");
}

__device__ __forceinline__ float sigfast(float x) {
    float e = __expf(-x);
    return __fdividef(1.0f, 1.0f + e);
}
__device__ __forceinline__ float tanhfast(float x) {
    float ax = fabsf(x);
    float e = __expf(-2.0f * ax);
    float t = __fdividef(1.0f - e, 1.0f + e);
    return copysignf(t, x);
}

// chunk-padded h index: k -> (k/16)*20 + (k%16)
__device__ __forceinline__ int hIdx(int k) { return (k >> 4) * 20 + (k & 15); }

// broadcast one float to the same smem slot in all 4 cluster CTAs
__device__ __forceinline__ void push4(float v, float* dst) {
    uint32_t la = (uint32_t)__cvta_generic_to_shared(dst);
#pragma unroll
    for (int rr = 0; rr < NCTA; rr++) {
        uint32_t ra;
        asm volatile("mapa.shared::cluster.u32 %0, %1, %2;"
                     : "=r"(ra) : "r"(la), "r"(rr));
        asm volatile("st.shared::cluster.f32 [%0], %1;"
                     :: "r"(ra), "f"(v) : "memory");
    }
}

__device__ __forceinline__ float act2(float g0, float g1, float g2, float g3,
                                      float& c, bool first) {
    float ii = sigfast(g0), ff = sigfast(g1), tg = tanhfast(g2), oo = sigfast(g3);
    float cc = first ? ii * tg : fmaf(ff, c, ii * tg);
    c = cc;
    return oo * tanhfast(cc);
}

// reduce-scatter over ke (lane bits 0..2); v[0..3] per-batch partials.
// Result: lane holds total for batch b = 2*((lane>>2)&1) + ((lane>>1)&1).
__device__ __forceinline__ float rscat8(const float* v, int lane) {
    const bool k2 = (lane & 4) != 0, k1 = (lane & 2) != 0;
    float s0 = k2 ? v[0] : v[2];
    float s1 = k2 ? v[1] : v[3];
    float r0 = __shfl_xor_sync(0xFFFFFFFFu, s0, 4);
    float r1 = __shfl_xor_sync(0xFFFFFFFFu, s1, 4);
    float k0v = (k2 ? v[2] : v[0]) + r0;
    float k1v = (k2 ? v[3] : v[1]) + r1;
    float s2 = k1 ? k0v : k1v;
    float r2 = __shfl_xor_sync(0xFFFFFFFFu, s2, 2);
    float res = (k1 ? k1v : k0v) + r2;
    res += __shfl_xor_sync(0xFFFFFFFFu, res, 1);
    return res;
}

// One fused stage, fully in-warp after the matvec.
//   gates1 = Wih1·h0 (+ Whh1·h1 if HH1);  gates0 = Whh0·h0 (if G0)
template<bool HH1, bool G0, bool FIRST1>
__device__ __forceinline__ void stage(Smem& s, int pw, int lane,
                                      int lr, int ke, int t_next,
                                      float& c0, float& c1,
                                      float& h0last, float& h1last, int hix) {
    const float* w1 = &s.W1s[lr * PADW + ke * 16];
    const float* u1 = &s.U1s[lr * PADW + ke * 16];
    const float* u0 = &s.U0s[lr * PADW + ke * 16];
    const float* h0 = &s.h0buf[pw][ke * 20];
    const float* h1 = &s.h1buf[pw][ke * 20];
    ull A1[4] = {}, A0[4] = {};
#pragma unroll
    for (int k4 = 0; k4 < 4; k4++) {
        ulonglong2 W1v = *(const ulonglong2*)(w1 + 4 * k4);
        ulonglong2 U1v, U0v;
        if (HH1) U1v = *(const ulonglong2*)(u1 + 4 * k4);
        if (G0)  U0v = *(const ulonglong2*)(u0 + 4 * k4);
#pragma unroll
        for (int b = 0; b < 4; b++) {
            ulonglong2 H0 = *(const ulonglong2*)(h0 + b * HB + 4 * k4);
            FFMA2(A1[b], W1v.x, H0.x);
            FFMA2(A1[b], W1v.y, H0.y);
            if (G0) {
                FFMA2(A0[b], U0v.x, H0.x);
                FFMA2(A0[b], U0v.y, H0.y);
            }
            if (HH1) {
                ulonglong2 H1 = *(const ulonglong2*)(h1 + b * HB + 4 * k4);
                FFMA2(A1[b], U1v.x, H1.x);
                FFMA2(A1[b], U1v.y, H1.y);
            }
        }
    }
    float v1[4], v0[4];
#pragma unroll
    for (int b = 0; b < 4; b++) {
        v1[b] = hsum2(A1[b]);
        if (G0) v0[b] = hsum2(A0[b]);
    }
    float res1 = rscat8(v1, lane);
    float res0 = 0.0f;
    if (G0) res0 = rscat8(v0, lane);
    // gather 4 gates for batch b = lane (acting lanes 0..3)
    const int sb = ((lane & 2) << 1) | ((lane & 1) << 1);
    float G1[4], G0g[4];
#pragma unroll
    for (int g = 0; g < 4; g++) {
        G1[g] = __shfl_sync(0xFFFFFFFFu, res1, g * 8 + sb);
        if (G0) G0g[g] = __shfl_sync(0xFFFFFFFFu, res0, g * 8 + sb);
    }
    if (lane < 4) {
        const int b = lane;           // acting lanes have g = 0, so base row = lr
        float h1n = act2(G1[0] + s.b1s[lr + 0], G1[1] + s.b1s[lr + 1],
                         G1[2] + s.b1s[lr + 2], G1[3] + s.b1s[lr + 3],
                         c1, FIRST1);
        h1last = h1n;
        push4(h1n, &s.h1buf[pw ^ 1][b * HB + hix]);
        if (G0) {
            const float* x = &s.xin[(t_next * 4 + b) * 4];
            float gg[4];
#pragma unroll
            for (int g = 0; g < 4; g++) {
                const float* wv = &s.W0s[(lr + g) * 4];
                gg[g] = G0g[g] + s.b0s[lr + g]
                      + wv[0] * x[0] + wv[1] * x[1] + wv[2] * x[2];
            }
            float h0n = act2(gg[0], gg[1], gg[2], gg[3], c0, false);
            h0last = h0n;
            push4(h0n, &s.h0buf[pw ^ 1][b * HB + hix]);
        }
    }
}

extern __shared__ float smem_raw[];

__global__ void __cluster_dims__(NCTA, 1, 1) __launch_bounds__(NTHREADS, 1)
lstm_kernel(const float* __restrict__ traj,
            const float* __restrict__ Wih0, const float* __restrict__ Whh0,
            const float* __restrict__ bih0, const float* __restrict__ bhh0,
            const float* __restrict__ Wih1, const float* __restrict__ Whh1,
            const float* __restrict__ bih1, const float* __restrict__ bhh1,
            const float* __restrict__ Wl,   const float* __restrict__ bl,
            float* __restrict__ out) {
    Smem& s = *reinterpret_cast<Smem*>(smem_raw);
    const int tid = threadIdx.x;
    uint32_t rank;
    asm("mov.u32 %0, %%cluster_ctarank;" : "=r"(rank));
    const int cluster = blockIdx.x / NCTA;
    const int gb0 = cluster * 4;

    // ---- weights: local row lr = wid*4 + g  <->  global gr = g*128 + rank*32 + wid
    for (int i = tid; i < 128 * HID; i += NTHREADS) {
        int lr = i / HID, k = i % HID;
        int wl = lr >> 2, g = lr & 3;
        int gr = g * 128 + (int)rank * 32 + wl;
        s.W1s[lr * PADW + k] = Wih1[gr * HID + k];
        s.U1s[lr * PADW + k] = Whh1[gr * HID + k];
        s.U0s[lr * PADW + k] = Whh0[gr * HID + k];
    }
    for (int lr = tid; lr < 128; lr += NTHREADS) {
        int wl = lr >> 2, g = lr & 3;
        int gr = g * 128 + (int)rank * 32 + wl;
        s.W0s[lr * 4 + 0] = Wih0[gr * 3 + 0];
        s.W0s[lr * 4 + 1] = Wih0[gr * 3 + 1];
        s.W0s[lr * 4 + 2] = Wih0[gr * 3 + 2];
        s.W0s[lr * 4 + 3] = 0.0f;
        s.b0s[lr] = bih0[gr] + bhh0[gr];
        s.b1s[lr] = bih1[gr] + bhh1[gr];
    }
    for (int i = tid; i < 2 * HID; i += NTHREADS) s.Wl[i] = Wl[i];
    if (tid < 2) s.bl[tid] = bl[tid];

    // ---- build xin for window 0 (raw trajectory rows 0..3)
    if (tid < 64) {
        int t = tid >> 4, b = (tid >> 2) & 3, f = tid & 3;
        if (f < 3) s.xin[(t * 4 + b) * 4 + f] = traj[((gb0 + b) * TT + t) * 3 + f];
    }
    __syncthreads();
    cluster_sync_all();

    const int wid  = tid >> 5;       // warp = unit in CTA (0..31)
    const int lane = tid & 31;
    const int ke   = lane & 7;       // k-eighth (16 k values)
    const int lr   = wid * 4 + (lane >> 3);   // this lane's gate row
    const int jg   = (int)rank * 32 + wid;    // global hidden index of warp's unit
    const int hix  = hIdx(jg);

    int pw = 0;
    float c0 = 0.f, c1 = 0.f, h0last = 0.f, h1last = 0.f;

    for (int w = 0; w < NWIN; w++) {
        // ---- s0: layer-0 @ t=0 (x only), acting lanes of every warp
        if (lane < 4) {
            int b = lane;
            const float* x = &s.xin[(0 * 4 + b) * 4];
            float g4[4];
#pragma unroll
            for (int g = 0; g < 4; g++) {
                const float* wv = &s.W0s[(wid * 4 + g) * 4];
                g4[g] = s.b0s[wid * 4 + g]
                      + wv[0] * x[0] + wv[1] * x[1] + wv[2] * x[2];
            }
            float h0n = act2(g4[0], g4[1], g4[2], g4[3], c0, true);
            h0last = h0n;
            push4(h0n, &s.h0buf[pw ^ 1][b * HB + hix]);
        }
        cluster_sync_all();
        pw ^= 1;

        // ---- s1..s3: fused L1[t] + L0[t+1];  s4: L1[3] only — one barrier each
        stage<false, true, true >(s, pw, lane, lr, ke, 1, c0, c1, h0last, h1last, hix);
        cluster_sync_all(); pw ^= 1;
        stage<true,  true, false>(s, pw, lane, lr, ke, 2, c0, c1, h0last, h1last, hix);
        cluster_sync_all(); pw ^= 1;
        stage<true,  true, false>(s, pw, lane, lr, ke, 3, c0, c1, h0last, h1last, hix);
        cluster_sync_all(); pw ^= 1;
        stage<true,  false, false>(s, pw, lane, lr, ke, 0, c0, c1, h0last, h1last, hix);
        cluster_sync_all(); pw ^= 1;

        // ---- head: pred[b][o] = Wl[o,:]·h1[b,:] + bl[o]   (8 warps)
        if (tid < 256) {
            int hw = tid >> 5;
            int b = hw >> 1, o = hw & 1;
            const float4* wl4 = (const float4*)&s.Wl[o * HID];
            float4 a = wl4[lane];
            const float* hb = &s.h1buf[pw][b * HB + (lane >> 2) * 20 + (lane & 3) * 4];
            float4 hh = *(const float4*)hb;
            float p = a.x * hh.x + a.y * hh.y + a.z * hh.z + a.w * hh.w;
            p += __shfl_xor_sync(0xFFFFFFFFu, p, 16);
            p += __shfl_xor_sync(0xFFFFFFFFu, p, 8);
            p += __shfl_xor_sync(0xFFFFFFFFu, p, 4);
            p += __shfl_xor_sync(0xFFFFFFFFu, p, 2);
            p += __shfl_xor_sync(0xFFFFFFFFu, p, 1);
            if (lane == 0) s.pred[b * 2 + o] = p + s.bl[o];
        }
        __syncthreads();

        // ---- pred writer + next-window xin builder (ring winbuf, no shift)
        const int wn = w + 1;
        if (tid < 64) {
            int t = tid >> 4, b = (tid >> 2) & 3, f = tid & 3;
            if (f < 3) {
                int gb = gb0 + b;
                float v;
                if (wn < 4) {
                    if (t < 3) v = traj[(gb * TT + (wn + t)) * 3 + f];
                    else if (f == 0) v = traj[(gb * TT + (4 + wn)) * 3 + 0];
                    else v = traj[(gb * TT + 3 + w) * 3 + f] + s.pred[b * 2 + (f - 1)];
                } else {
                    if (f < 2) {
                        if (t < 3) v = s.winbuf[(b * 4 + ((wn + t) & 3)) * 2 + f];
                        else {
                            float base = (w < 4)
                                ? traj[(gb * TT + 3 + w) * 3 + 1 + f]
                                : s.winbuf[(b * 4 + ((w + 3) & 3)) * 2 + f];
                            v = base + s.pred[b * 2 + f];
                        }
                    } else v = traj[(gb * TT + (wn + t)) * 3 + 0];
                }
                s.xin[(t * 4 + b) * 4 + f] = v;
            }
        } else if (tid < 72) {
            int t2 = tid - 64;
            int b = t2 >> 1, o = t2 & 1;
            int gb = gb0 + b;
            float base = (w < 4) ? traj[(gb * TT + 3 + w) * 3 + 1 + o]
                                 : s.winbuf[(b * 4 + ((w + 3) & 3)) * 2 + o];
            float pn = base + s.pred[b * 2 + o];
            s.winbuf[(b * 4 + (w & 3)) * 2 + o] = pn;
            if (rank == 0) out[(gb * NWIN + w) * 2 + o] = pn;
        }
        __syncthreads();
    }

    // ---- final hidden/cell states from acting-lane registers
    if (lane < 4) {
        int b = lane;
        int gb = gb0 + b;
        const int OFF_H = 128 * NWIN * 2;          // 64512
        const int OFF_C = OFF_H + 2 * 128 * HID;   // 97280
        out[OFF_H + 0 * 128 * HID + gb * HID + jg] = h0last;
        out[OFF_H + 1 * 128 * HID + gb * HID + jg] = h1last;
        out[OFF_C + 0 * 128 * HID + gb * HID + jg] = c0;
        out[OFF_C + 1 * 128 * HID + gb * HID + jg] = c1;
    }
}

extern "C" void kernel_launch(void* const* d_in, const int* in_sizes, int n_in,
                              void* d_out, int out_size) {
    const float* traj = (const float*)d_in[0];
    const float* Wih0 = (const float*)d_in[1];
    const float* Whh0 = (const float*)d_in[2];
    const float* bih0 = (const float*)d_in[3];
    const float* bhh0 = (const float*)d_in[4];
    const float* Wih1 = (const float*)d_in[5];
    const float* Whh1 = (const float*)d_in[6];
    const float* bih1 = (const float*)d_in[7];
    const float* bhh1 = (const float*)d_in[8];
    const float* Wl   = (const float*)d_in[9];
    const float* bl   = (const float*)d_in[10];
    float* out = (float*)d_out;

    int smem = (int)sizeof(Smem);
    cudaFuncSetAttribute(lstm_kernel, cudaFuncAttributeMaxDynamicSharedMemorySize, smem);
    lstm_kernel<<<128, NTHREADS, smem>>>(traj, Wih0, Whh0, bih0, bhh0,
                                         Wih1, Whh1, bih1, bhh1, Wl, bl, out);
}

// round 14
// speedup vs baseline: 1.6938x; 1.6938x over previous
#include <cuda_runtime.h>
#include <cstdint>

typedef unsigned long long ull;

#define NCTA      4
#define HID       128
#define NTHREADS  512
#define NWIN      252
#define TT        256
#define PADW      132     // weight row stride (floats)
#define HB        144     // per-batch h stride: 4 chunks of (32 data + 4 pad)
#define ARRIVALS  512     // 8 acting lanes x 16 warps x 4 CTAs per phase

// row layout: lr = w*8 + g*2 + j   (warp w owns units au=2w+j, j in {0,1})
struct Smem {
    ull   mbar[2];           // phase-ring mbarriers
    float W1s[128 * PADW];   // Wih1
    float U1s[128 * PADW];   // Whh1
    float U0s[128 * PADW];   // Whh0
    float W0s[128 * 4];      // Wih0 (3 cols + pad)
    float b0s[128];
    float b1s[128];
    float h0buf[2][4 * HB];  // ping-pong, cluster-shared, chunk-padded
    float h1buf[2][4 * HB];
    float xin[4 * 4 * 4];    // [t][b][f pad4]
    float Wl[2 * HID];
    float winbuf[4 * 4 * 2];
    float pred[4 * 2];
    float bl[2];
};

#define FFMA2(acc, w, h) \
    asm("fma.rn.f32x2 %0, %1, %2, %0;" : "+l"(acc) : "l"(w), "l"(h))

__device__ __forceinline__ float hsum2(ull a) {
    float lo, hi;
    asm("mov.b64 {%0, %1}, %2;" : "=f"(lo), "=f"(hi) : "l"(a));
    return lo + hi;
}

__device__ __forceinline__ void cluster_sync_all() {
    asm volatile("barrier.cluster.arrive.aligned;" ::: "memory");
    asm volatile("barrier.cluster.wait.aligned;" ::: "memory");
}

__device__ __forceinline__ uint32_t smem_u32(const void* p) {
    uint32_t a;
    asm("{ .reg .u64 t; cvta.to.shared.u64 t, %1; cvt.u32.u64 %0, t; }"
        : "=r"(a) : "l"(p));
    return a;
}

// producer: arrive (release, cluster scope) on the same mbarrier slot in all 4 CTAs
__device__ __forceinline__ void arrive4(uint32_t mbar_la) {
#pragma unroll
    for (int rr = 0; rr < NCTA; rr++) {
        uint32_t ra;
        asm volatile("mapa.shared::cluster.u32 %0, %1, %2;"
                     : "=r"(ra) : "r"(mbar_la), "r"(rr));
        asm volatile("mbarrier.arrive.release.cluster.shared::cluster.b64 _, [%0];"
                     :: "r"(ra) : "memory");
    }
}

// consumer: wait on local mbarrier phase (acquire, cluster scope)
__device__ __forceinline__ void phase_wait(uint32_t mbar_la, uint32_t parity) {
    uint32_t done;
    do {
        asm volatile(
            "{\n\t.reg .pred p;\n\t"
            "mbarrier.try_wait.parity.acquire.cluster.shared::cta.b64 p, [%1], %2, 0x989680;\n\t"
            "selp.b32 %0, 1, 0, p;\n\t}"
            : "=r"(done) : "r"(mbar_la), "r"(parity) : "memory");
    } while (!done);
}

__device__ __forceinline__ float sigfast(float x) {
    float e = __expf(-x);
    return __fdividef(1.0f, 1.0f + e);
}
__device__ __forceinline__ float tanhfast(float x) {
    float ax = fabsf(x);
    float e = __expf(-2.0f * ax);
    float t = __fdividef(1.0f - e, 1.0f + e);
    return copysignf(t, x);
}

// chunk-padded h index: k -> (k/32)*36 + (k%32)
__device__ __forceinline__ int hIdx(int k) { return (k >> 5) * 36 + (k & 31); }

// broadcast one float to the same smem slot in all 4 cluster CTAs
__device__ __forceinline__ void push4(float v, float* dst) {
    uint32_t la = (uint32_t)__cvta_generic_to_shared(dst);
#pragma unroll
    for (int rr = 0; rr < NCTA; rr++) {
        uint32_t ra;
        asm volatile("mapa.shared::cluster.u32 %0, %1, %2;"
                     : "=r"(ra) : "r"(la), "r"(rr));
        asm volatile("st.shared::cluster.f32 [%0], %1;"
                     :: "r"(ra), "f"(v) : "memory");
    }
}

__device__ __forceinline__ float act2(float g0, float g1, float g2, float g3,
                                      float& c, bool first) {
    float ii = sigfast(g0), ff = sigfast(g1), tg = tanhfast(g2), oo = sigfast(g3);
    float cc = first ? ii * tg : fmaf(ff, c, ii * tg);
    c = cc;
    return oo * tanhfast(cc);
}

// reduce-scatter over kq (lane bits 3,4): in g[0..3] per-batch partials,
// out: this lane's total for batch b = lane>>3.
__device__ __forceinline__ float rscat4(const float* g, int lane) {
    const bool b4 = (lane & 16) != 0, b3 = (lane & 8) != 0;
    float s0 = b4 ? g[0] : g[2];
    float s1 = b4 ? g[1] : g[3];
    float r0 = __shfl_xor_sync(0xFFFFFFFFu, s0, 16);
    float r1 = __shfl_xor_sync(0xFFFFFFFFu, s1, 16);
    float k0 = (b4 ? g[2] : g[0]) + r0;
    float k1 = (b4 ? g[3] : g[1]) + r1;
    float s2 = b3 ? k0 : k1;
    float r2 = __shfl_xor_sync(0xFFFFFFFFu, s2, 8);
    return (b3 ? k1 : k0) + r2;
}

// One fused stage, fully in-warp after the matvec:
//   gates1 = Wih1·h0 (+ Whh1·h1 if HH1);  gates0 = Whh0·h0 (if G0)
// acting lanes: activation + DSMEM push + mbarrier arrive.
template<bool HH1, bool G0, bool FIRST1>
__device__ __forceinline__ void stage(Smem& s, int pw, int wid, int lane,
                                      int kq, int rl, int t_next,
                                      float& c0, float& c1,
                                      float& h0last, float& h1last, int hix,
                                      uint32_t mla) {
    const int lr = wid * 8 + rl;
    const float* w1 = &s.W1s[lr * PADW + kq * 32];
    const float* u1 = &s.U1s[lr * PADW + kq * 32];
    const float* u0 = &s.U0s[lr * PADW + kq * 32];
    const float* h0 = &s.h0buf[pw][kq * 36];
    const float* h1 = &s.h1buf[pw][kq * 36];
    ull A1[4] = {}, A0[4] = {};
#pragma unroll
    for (int k4 = 0; k4 < 8; k4++) {
        ulonglong2 W1v = *(const ulonglong2*)(w1 + 4 * k4);
        ulonglong2 U1v, U0v;
        if (HH1) U1v = *(const ulonglong2*)(u1 + 4 * k4);
        if (G0)  U0v = *(const ulonglong2*)(u0 + 4 * k4);
#pragma unroll
        for (int b = 0; b < 4; b++) {
            ulonglong2 H0 = *(const ulonglong2*)(h0 + b * HB + 4 * k4);
            FFMA2(A1[b], W1v.x, H0.x);
            FFMA2(A1[b], W1v.y, H0.y);
            if (G0) {
                FFMA2(A0[b], U0v.x, H0.x);
                FFMA2(A0[b], U0v.y, H0.y);
            }
            if (HH1) {
                ulonglong2 H1 = *(const ulonglong2*)(h1 + b * HB + 4 * k4);
                FFMA2(A1[b], U1v.x, H1.x);
                FFMA2(A1[b], U1v.y, H1.y);
            }
        }
    }
    float g1v[4], g0v[4];
#pragma unroll
    for (int b = 0; b < 4; b++) {
        g1v[b] = hsum2(A1[b]);
        if (G0) g0v[b] = hsum2(A0[b]);
    }
    float res1 = rscat4(g1v, lane);
    float res0 = 0.0f;
    if (G0) res0 = rscat4(g0v, lane);
    // gather 4 gates for (unit j=lane&1, batch b=lane>>3) from same-kq lanes
    float G1[4], G0g[4];
#pragma unroll
    for (int g = 0; g < 4; g++) {
        int src = (lane & 24) | (g * 2 + (lane & 1));
        G1[g] = __shfl_sync(0xFFFFFFFFu, res1, src);
        if (G0) G0g[g] = __shfl_sync(0xFFFFFFFFu, res0, src);
    }
    if ((lane & 7) < 2) {
        const int b = lane >> 3, j = lane & 1;
        const int lrb = wid * 8 + j;
        float h1n = act2(G1[0] + s.b1s[lrb + 0], G1[1] + s.b1s[lrb + 2],
                         G1[2] + s.b1s[lrb + 4], G1[3] + s.b1s[lrb + 6],
                         c1, FIRST1);
        h1last = h1n;
        push4(h1n, &s.h1buf[pw ^ 1][b * HB + hix]);
        if (G0) {
            const float* x = &s.xin[(t_next * 4 + b) * 4];
            float gg[4];
#pragma unroll
            for (int g = 0; g < 4; g++) {
                int lr2 = lrb + g * 2;
                const float* wv = &s.W0s[lr2 * 4];
                gg[g] = G0g[g] + s.b0s[lr2]
                      + wv[0] * x[0] + wv[1] * x[1] + wv[2] * x[2];
            }
            float h0n = act2(gg[0], gg[1], gg[2], gg[3], c0, false);
            h0last = h0n;
            push4(h0n, &s.h0buf[pw ^ 1][b * HB + hix]);
        }
        arrive4(mla);
    }
}

extern __shared__ float smem_raw[];

__global__ void __cluster_dims__(NCTA, 1, 1) __launch_bounds__(NTHREADS, 1)
lstm_kernel(const float* __restrict__ traj,
            const float* __restrict__ Wih0, const float* __restrict__ Whh0,
            const float* __restrict__ bih0, const float* __restrict__ bhh0,
            const float* __restrict__ Wih1, const float* __restrict__ Whh1,
            const float* __restrict__ bih1, const float* __restrict__ bhh1,
            const float* __restrict__ Wl,   const float* __restrict__ bl,
            float* __restrict__ out) {
    Smem& s = *reinterpret_cast<Smem*>(smem_raw);
    const int tid = threadIdx.x;
    uint32_t rank;
    asm("mov.u32 %0, %%cluster_ctarank;" : "=r"(rank));
    const int cluster = blockIdx.x / NCTA;
    const int gb0 = cluster * 4;

    // ---- mbarrier init (count = arrivals per phase)
    if (tid == 0) {
        uint32_t m0 = smem_u32(&s.mbar[0]);
        uint32_t m1 = smem_u32(&s.mbar[1]);
        asm volatile("mbarrier.init.shared.b64 [%0], %1;" :: "r"(m0), "r"(ARRIVALS) : "memory");
        asm volatile("mbarrier.init.shared.b64 [%0], %1;" :: "r"(m1), "r"(ARRIVALS) : "memory");
    }

    // ---- weights: local row lr = w*8 + g*2 + j  <->  global gr = g*128 + rank*32 + 2w+j
    for (int i = tid; i < 128 * HID; i += NTHREADS) {
        int lr = i / HID, k = i % HID;
        int wv = lr >> 3, rl = lr & 7, g = rl >> 1, j = rl & 1;
        int gr = g * 128 + (int)rank * 32 + 2 * wv + j;
        s.W1s[lr * PADW + k] = Wih1[gr * HID + k];
        s.U1s[lr * PADW + k] = Whh1[gr * HID + k];
        s.U0s[lr * PADW + k] = Whh0[gr * HID + k];
    }
    for (int lr = tid; lr < 128; lr += NTHREADS) {
        int wv = lr >> 3, rl = lr & 7, g = rl >> 1, j = rl & 1;
        int gr = g * 128 + (int)rank * 32 + 2 * wv + j;
        s.W0s[lr * 4 + 0] = Wih0[gr * 3 + 0];
        s.W0s[lr * 4 + 1] = Wih0[gr * 3 + 1];
        s.W0s[lr * 4 + 2] = Wih0[gr * 3 + 2];
        s.W0s[lr * 4 + 3] = 0.0f;
        s.b0s[lr] = bih0[gr] + bhh0[gr];
        s.b1s[lr] = bih1[gr] + bhh1[gr];
    }
    for (int i = tid; i < 2 * HID; i += NTHREADS) s.Wl[i] = Wl[i];
    if (tid < 2) s.bl[tid] = bl[tid];
    __syncthreads();
    cluster_sync_all();   // mbarrier inits + weight tiles visible cluster-wide

    const uint32_t mb[2] = { smem_u32(&s.mbar[0]), smem_u32(&s.mbar[1]) };

    const int wid  = tid >> 5;
    const int lane = tid & 31;
    const int kq   = lane >> 3;      // k-quarter
    const int rl   = lane & 7;       // row within warp = g*2+j
    const int au  = 2 * wid + (lane & 1);
    const int jg  = (int)rank * 32 + au;
    const int hix = hIdx(jg);

    int pw = 0;
    int ph = 0;                      // global phase counter
    float c0 = 0.f, c1 = 0.f, h0last = 0.f, h1last = 0.f;

    for (int w = 0; w < NWIN; w++) {
        // ---- build window inputs xin[t][b][f]
        if (tid < 64) {
            int t = tid >> 4, b = (tid >> 2) & 3, f = tid & 3;
            if (f < 3) {
                int gb = gb0 + b;
                float v;
                if (w == 0) {
                    v = traj[(gb * TT + t) * 3 + f];
                } else if (w < 4) {
                    if (t < 3) v = traj[(gb * TT + (w + t)) * 3 + f];
                    else v = (f == 0) ? traj[(gb * TT + (4 + w)) * 3 + 0]
                                      : s.winbuf[(b * 4 + 3) * 2 + (f - 1)];
                } else {
                    v = (f < 2) ? s.winbuf[(b * 4 + t) * 2 + f]
                                : traj[(gb * TT + (w + t)) * 3 + 0];
                }
                s.xin[(t * 4 + b) * 4 + f] = v;
            }
        }
        __syncthreads();

        // ---- s0: layer-0 @ t=0 (x only), acting lanes of every warp
        {
            uint32_t mla = mb[ph & 1];
            uint32_t par = (ph >> 1) & 1;
            if ((lane & 7) < 2) {
                int b = lane >> 3, j = lane & 1;
                const float* x = &s.xin[(0 * 4 + b) * 4];
                float g4[4];
#pragma unroll
                for (int g = 0; g < 4; g++) {
                    int lr = wid * 8 + g * 2 + j;
                    const float* wv = &s.W0s[lr * 4];
                    g4[g] = s.b0s[lr] + wv[0] * x[0] + wv[1] * x[1] + wv[2] * x[2];
                }
                float h0n = act2(g4[0], g4[1], g4[2], g4[3], c0, true);
                h0last = h0n;
                push4(h0n, &s.h0buf[pw ^ 1][b * HB + hix]);
                arrive4(mla);
            }
            phase_wait(mla, par);
            ph++; pw ^= 1;
        }

        // ---- s1..s3: fused L1[t] + L0[t+1];  s4: L1[3] only — one phase each
        {
            uint32_t mla = mb[ph & 1]; uint32_t par = (ph >> 1) & 1;
            stage<false, true, true >(s, pw, wid, lane, kq, rl, 1, c0, c1, h0last, h1last, hix, mla);
            phase_wait(mla, par); ph++; pw ^= 1;
        }
        {
            uint32_t mla = mb[ph & 1]; uint32_t par = (ph >> 1) & 1;
            stage<true,  true, false>(s, pw, wid, lane, kq, rl, 2, c0, c1, h0last, h1last, hix, mla);
            phase_wait(mla, par); ph++; pw ^= 1;
        }
        {
            uint32_t mla = mb[ph & 1]; uint32_t par = (ph >> 1) & 1;
            stage<true,  true, false>(s, pw, wid, lane, kq, rl, 3, c0, c1, h0last, h1last, hix, mla);
            phase_wait(mla, par); ph++; pw ^= 1;
        }
        {
            uint32_t mla = mb[ph & 1]; uint32_t par = (ph >> 1) & 1;
            stage<true,  false, false>(s, pw, wid, lane, kq, rl, 0, c0, c1, h0last, h1last, hix, mla);
            phase_wait(mla, par); ph++; pw ^= 1;
        }

        // ---- head: pred[b][o] = Wl[o,:]·h1[b,:] + bl[o]
        if (tid < 256) {
            int hw = tid >> 5;
            int b = hw >> 1, o = hw & 1;
            const float4* wl4 = (const float4*)&s.Wl[o * HID];
            float4 a = wl4[lane];
            const float* hb = &s.h1buf[pw][b * HB + (lane >> 3) * 36 + (lane & 7) * 4];
            float4 hh = *(const float4*)hb;
            float p = a.x * hh.x + a.y * hh.y + a.z * hh.z + a.w * hh.w;
            p += __shfl_xor_sync(0xFFFFFFFFu, p, 16);
            p += __shfl_xor_sync(0xFFFFFFFFu, p, 8);
            p += __shfl_xor_sync(0xFFFFFFFFu, p, 4);
            p += __shfl_xor_sync(0xFFFFFFFFu, p, 2);
            p += __shfl_xor_sync(0xFFFFFFFFu, p, 1);
            if (lane == 0) s.pred[b * 2 + o] = p + s.bl[o];
        }
        __syncthreads();
        if (tid < 8) {
            int b = tid >> 1, o = tid & 1;
            int gb = gb0 + b;
            float base = (w < 4) ? traj[(gb * TT + 3 + w) * 3 + 1 + o]
                                 : s.winbuf[(b * 4 + 3) * 2 + o];
            float pn = base + s.pred[b * 2 + o];
            float t1 = s.winbuf[(b * 4 + 1) * 2 + o];
            float t2 = s.winbuf[(b * 4 + 2) * 2 + o];
            float t3 = s.winbuf[(b * 4 + 3) * 2 + o];
            s.winbuf[(b * 4 + 0) * 2 + o] = t1;
            s.winbuf[(b * 4 + 1) * 2 + o] = t2;
            s.winbuf[(b * 4 + 2) * 2 + o] = t3;
            s.winbuf[(b * 4 + 3) * 2 + o] = pn;
            if (rank == 0) out[(gb * NWIN + w) * 2 + o] = pn;
        }
        __syncthreads();
    }

    // ---- final hidden/cell states from acting-lane registers
    if ((lane & 7) < 2) {
        int b = lane >> 3;
        int gb = gb0 + b;
        const int OFF_H = 128 * NWIN * 2;          // 64512
        const int OFF_C = OFF_H + 2 * 128 * HID;   // 97280
        out[OFF_H + 0 * 128 * HID + gb * HID + jg] = h0last;
        out[OFF_H + 1 * 128 * HID + gb * HID + jg] = h1last;
        out[OFF_C + 0 * 128 * HID + gb * HID + jg] = c0;
        out[OFF_C + 1 * 128 * HID + gb * HID + jg] = c1;
    }
}

extern "C" void kernel_launch(void* const* d_in, const int* in_sizes, int n_in,
                              void* d_out, int out_size) {
    const float* traj = (const float*)d_in[0];
    const float* Wih0 = (const float*)d_in[1];
    const float* Whh0 = (const float*)d_in[2];
    const float* bih0 = (const float*)d_in[3];
    const float* bhh0 = (const float*)d_in[4];
    const float* Wih1 = (const float*)d_in[5];
    const float* Whh1 = (const float*)d_in[6];
    const float* bih1 = (const float*)d_in[7];
    const float* bhh1 = (const float*)d_in[8];
    const float* Wl   = (const float*)d_in[9];
    const float* bl   = (const float*)d_in[10];
    float* out = (float*)d_out;

    int smem = (int)sizeof(Smem);
    cudaFuncSetAttribute(lstm_kernel, cudaFuncAttributeMaxDynamicSharedMemorySize, smem);
    lstm_kernel<<<128, NTHREADS, smem>>>(traj, Wih0, Whh0, bih0, bhh0,
                                         Wih1, Whh1, bih1, bhh1, Wl, bl, out);
}

// round 15
// speedup vs baseline: 2.3694x; 1.3988x over previous
#include <cuda_runtime.h>
#include <cstdint>

typedef unsigned long long ull;

#define NCTA      4
#define HID       128
#define NTHREADS  512
#define NWIN      252
#define TT        256
#define PADW      132     // weight row stride (floats)
#define HB        144     // per-batch h stride: 4 chunks of (32 data + 4 pad)

// row layout: lr = w*8 + g*2 + j   (warp w owns units au=2w+j, j in {0,1})
struct Smem {
    float W1s[128 * PADW];   // Wih1
    float U1s[128 * PADW];   // Whh1
    float U0s[128 * PADW];   // Whh0
    float W0s[128 * 4];      // Wih0 (3 cols + pad)
    float b0s[128];
    float b1s[128];
    float h0buf[2][4 * HB];  // ping-pong, cluster-shared, chunk-padded
    float h1buf[2][4 * HB];
    float xin[4 * 4 * 4];    // [t][b][f pad4], t=1..3 used
    float xt0[2][4 * 4];     // t=0 inputs, ping-pong by window parity
    float Wl[2 * HID];
    float winbuf[4 * 4 * 2]; // ring: [b][slot][o], pred of window p at slot p&3
    float pred[4 * 2];
    float bl[2];
};

#define FFMA2(acc, w, h) \
    asm("fma.rn.f32x2 %0, %1, %2, %0;" : "+l"(acc) : "l"(w), "l"(h))

__device__ __forceinline__ float hsum2(ull a) {
    float lo, hi;
    asm("mov.b64 {%0, %1}, %2;" : "=f"(lo), "=f"(hi) : "l"(a));
    return lo + hi;
}

__device__ __forceinline__ void cluster_sync_all() {
    asm volatile("barrier.cluster.arrive.aligned;" ::: "memory");
    asm volatile("barrier.cluster.wait.aligned;" ::: "memory");
}

__device__ __forceinline__ float sigfast(float x) {
    float e = __expf(-x);
    return __fdividef(1.0f, 1.0f + e);
}
__device__ __forceinline__ float tanhfast(float x) {
    float ax = fabsf(x);
    float e = __expf(-2.0f * ax);
    float t = __fdividef(1.0f - e, 1.0f + e);
    return copysignf(t, x);
}

// chunk-padded h index: k -> (k/32)*36 + (k%32)
__device__ __forceinline__ int hIdx(int k) { return (k >> 5) * 36 + (k & 31); }

// broadcast one float to the same smem slot in all 4 cluster CTAs
__device__ __forceinline__ void push4(float v, float* dst) {
    uint32_t la = (uint32_t)__cvta_generic_to_shared(dst);
#pragma unroll
    for (int rr = 0; rr < NCTA; rr++) {
        uint32_t ra;
        asm volatile("mapa.shared::cluster.u32 %0, %1, %2;"
                     : "=r"(ra) : "r"(la), "r"(rr));
        asm volatile("st.shared::cluster.f32 [%0], %1;"
                     :: "r"(ra), "f"(v) : "memory");
    }
}

__device__ __forceinline__ float act2(float g0, float g1, float g2, float g3,
                                      float& c, bool first) {
    float ii = sigfast(g0), ff = sigfast(g1), tg = tanhfast(g2), oo = sigfast(g3);
    float cc = first ? ii * tg : fmaf(ff, c, ii * tg);
    c = cc;
    return oo * tanhfast(cc);
}

// reduce-scatter over kq (lane bits 3,4): in g[0..3] per-batch partials,
// out: this lane's total for batch b = lane>>3.
__device__ __forceinline__ float rscat4(const float* g, int lane) {
    const bool b4 = (lane & 16) != 0, b3 = (lane & 8) != 0;
    float s0 = b4 ? g[0] : g[2];
    float s1 = b4 ? g[1] : g[3];
    float r0 = __shfl_xor_sync(0xFFFFFFFFu, s0, 16);
    float r1 = __shfl_xor_sync(0xFFFFFFFFu, s1, 16);
    float k0 = (b4 ? g[2] : g[0]) + r0;
    float k1 = (b4 ? g[3] : g[1]) + r1;
    float s2 = b3 ? k0 : k1;
    float r2 = __shfl_xor_sync(0xFFFFFFFFu, s2, 8);
    return (b3 ? k1 : k0) + r2;
}

// One fused stage, fully in-warp after the matvec:
//   gates1 = Wih1·h0 (+ Whh1·h1 if HH1);  gates0 = Whh0·h0 (if G0)
// If x0n != nullptr (s4 only): also compute next-window L0[t=0] (x-only,
// fresh cell state) in the acting lanes.
template<bool HH1, bool G0, bool FIRST1>
__device__ __forceinline__ void stage(Smem& s, int pw, int wid, int lane,
                                      int kq, int rl, int t_next,
                                      float& c0, float& c1,
                                      float& h0last, float& h1last, int hix,
                                      const float* x0n) {
    const int lr = wid * 8 + rl;
    const float* w1 = &s.W1s[lr * PADW + kq * 32];
    const float* u1 = &s.U1s[lr * PADW + kq * 32];
    const float* u0 = &s.U0s[lr * PADW + kq * 32];
    const float* h0 = &s.h0buf[pw][kq * 36];
    const float* h1 = &s.h1buf[pw][kq * 36];
    ull A1[4] = {}, A0[4] = {};
#pragma unroll
    for (int k4 = 0; k4 < 8; k4++) {
        ulonglong2 W1v = *(const ulonglong2*)(w1 + 4 * k4);
        ulonglong2 U1v, U0v;
        if (HH1) U1v = *(const ulonglong2*)(u1 + 4 * k4);
        if (G0)  U0v = *(const ulonglong2*)(u0 + 4 * k4);
#pragma unroll
        for (int b = 0; b < 4; b++) {
            ulonglong2 H0 = *(const ulonglong2*)(h0 + b * HB + 4 * k4);
            FFMA2(A1[b], W1v.x, H0.x);
            FFMA2(A1[b], W1v.y, H0.y);
            if (G0) {
                FFMA2(A0[b], U0v.x, H0.x);
                FFMA2(A0[b], U0v.y, H0.y);
            }
            if (HH1) {
                ulonglong2 H1 = *(const ulonglong2*)(h1 + b * HB + 4 * k4);
                FFMA2(A1[b], U1v.x, H1.x);
                FFMA2(A1[b], U1v.y, H1.y);
            }
        }
    }
    float g1v[4], g0v[4];
#pragma unroll
    for (int b = 0; b < 4; b++) {
        g1v[b] = hsum2(A1[b]);
        if (G0) g0v[b] = hsum2(A0[b]);
    }
    float res1 = rscat4(g1v, lane);
    float res0 = 0.0f;
    if (G0) res0 = rscat4(g0v, lane);
    // gather 4 gates for (unit j=lane&1, batch b=lane>>3) from same-kq lanes
    float G1[4], G0g[4];
#pragma unroll
    for (int g = 0; g < 4; g++) {
        int src = (lane & 24) | (g * 2 + (lane & 1));
        G1[g] = __shfl_sync(0xFFFFFFFFu, res1, src);
        if (G0) G0g[g] = __shfl_sync(0xFFFFFFFFu, res0, src);
    }
    if ((lane & 7) < 2) {
        const int b = lane >> 3, j = lane & 1;
        const int lrb = wid * 8 + j;
        float h1n = act2(G1[0] + s.b1s[lrb + 0], G1[1] + s.b1s[lrb + 2],
                         G1[2] + s.b1s[lrb + 4], G1[3] + s.b1s[lrb + 6],
                         c1, FIRST1);
        h1last = h1n;
        push4(h1n, &s.h1buf[pw ^ 1][b * HB + hix]);
        if (G0) {
            const float* x = &s.xin[(t_next * 4 + b) * 4];
            float gg[4];
#pragma unroll
            for (int g = 0; g < 4; g++) {
                int lr2 = lrb + g * 2;
                const float* wv = &s.W0s[lr2 * 4];
                gg[g] = G0g[g] + s.b0s[lr2]
                      + wv[0] * x[0] + wv[1] * x[1] + wv[2] * x[2];
            }
            float h0n = act2(gg[0], gg[1], gg[2], gg[3], c0, false);
            h0last = h0n;
            push4(h0n, &s.h0buf[pw ^ 1][b * HB + hix]);
        }
        if (x0n) {   // fused next-window L0[t=0]: x-only, fresh cell
            const float* x = x0n + b * 4;
            float gg[4];
#pragma unroll
            for (int g = 0; g < 4; g++) {
                int lr2 = lrb + g * 2;
                const float* wv = &s.W0s[lr2 * 4];
                gg[g] = s.b0s[lr2]
                      + wv[0] * x[0] + wv[1] * x[1] + wv[2] * x[2];
            }
            float h0n = act2(gg[0], gg[1], gg[2], gg[3], c0, true);
            h0last = h0n;
            push4(h0n, &s.h0buf[pw ^ 1][b * HB + hix]);
        }
    }
}

extern __shared__ float smem_raw[];

__global__ void __cluster_dims__(NCTA, 1, 1) __launch_bounds__(NTHREADS, 1)
lstm_kernel(const float* __restrict__ traj,
            const float* __restrict__ Wih0, const float* __restrict__ Whh0,
            const float* __restrict__ bih0, const float* __restrict__ bhh0,
            const float* __restrict__ Wih1, const float* __restrict__ Whh1,
            const float* __restrict__ bih1, const float* __restrict__ bhh1,
            const float* __restrict__ Wl,   const float* __restrict__ bl,
            float* __restrict__ out) {
    Smem& s = *reinterpret_cast<Smem*>(smem_raw);
    const int tid = threadIdx.x;
    uint32_t rank;
    asm("mov.u32 %0, %%cluster_ctarank;" : "=r"(rank));
    const int cluster = blockIdx.x / NCTA;
    const int gb0 = cluster * 4;

    // ---- weights: local row lr = w*8 + g*2 + j  <->  global gr = g*128 + rank*32 + 2w+j
    for (int i = tid; i < 128 * HID; i += NTHREADS) {
        int lr = i / HID, k = i % HID;
        int wv = lr >> 3, rl = lr & 7, g = rl >> 1, j = rl & 1;
        int gr = g * 128 + (int)rank * 32 + 2 * wv + j;
        s.W1s[lr * PADW + k] = Wih1[gr * HID + k];
        s.U1s[lr * PADW + k] = Whh1[gr * HID + k];
        s.U0s[lr * PADW + k] = Whh0[gr * HID + k];
    }
    for (int lr = tid; lr < 128; lr += NTHREADS) {
        int wv = lr >> 3, rl = lr & 7, g = rl >> 1, j = rl & 1;
        int gr = g * 128 + (int)rank * 32 + 2 * wv + j;
        s.W0s[lr * 4 + 0] = Wih0[gr * 3 + 0];
        s.W0s[lr * 4 + 1] = Wih0[gr * 3 + 1];
        s.W0s[lr * 4 + 2] = Wih0[gr * 3 + 2];
        s.W0s[lr * 4 + 3] = 0.0f;
        s.b0s[lr] = bih0[gr] + bhh0[gr];
        s.b1s[lr] = bih1[gr] + bhh1[gr];
    }
    for (int i = tid; i < 2 * HID; i += NTHREADS) s.Wl[i] = Wl[i];
    if (tid < 2) s.bl[tid] = bl[tid];

    // ---- prologue inputs: xin[1..3] of window 0 (traj rows 1..3),
    //      xt0[0] (window 0 t=0 = traj row 0), xt0[1] (window 1 t=0 = traj row 1)
    if (tid < 64) {
        int t = tid >> 4, b = (tid >> 2) & 3, f = tid & 3;
        if (f < 3) {
            int gb = gb0 + b;
            if (t >= 1) s.xin[(t * 4 + b) * 4 + f] = traj[(gb * TT + t) * 3 + f];
            else {
                s.xt0[0][b * 4 + f] = traj[(gb * TT + 0) * 3 + f];
                s.xt0[1][b * 4 + f] = traj[(gb * TT + 1) * 3 + f];
            }
        }
    }
    __syncthreads();

    const int wid  = tid >> 5;
    const int lane = tid & 31;
    const int kq   = lane >> 3;      // k-quarter
    const int rl   = lane & 7;       // row within warp = g*2+j
    const int au  = 2 * wid + (lane & 1);
    const int jg  = (int)rank * 32 + au;
    const int hix = hIdx(jg);

    int pw = 0;
    float c0 = 0.f, c1 = 0.f, h0last = 0.f, h1last = 0.f;

    // ---- prologue s0: L0[t=0] of window 0 (x only)
    if ((lane & 7) < 2) {
        int b = lane >> 3, j = lane & 1;
        const float* x = &s.xt0[0][b * 4];
        float g4[4];
#pragma unroll
        for (int g = 0; g < 4; g++) {
            int lr = wid * 8 + g * 2 + j;
            const float* wv = &s.W0s[lr * 4];
            g4[g] = s.b0s[lr] + wv[0] * x[0] + wv[1] * x[1] + wv[2] * x[2];
        }
        float h0n = act2(g4[0], g4[1], g4[2], g4[3], c0, true);
        h0last = h0n;
        push4(h0n, &s.h0buf[pw ^ 1][b * HB + hix]);
    }
    cluster_sync_all();
    pw ^= 1;

    for (int w = 0; w < NWIN; w++) {
        // ---- 4 phases: s1..s3 fused L1[t]+L0[t+1]; s4 = L1[3] + next L0[0]
        stage<false, true, true >(s, pw, wid, lane, kq, rl, 1, c0, c1, h0last, h1last, hix, nullptr);
        cluster_sync_all(); pw ^= 1;
        stage<true,  true, false>(s, pw, wid, lane, kq, rl, 2, c0, c1, h0last, h1last, hix, nullptr);
        cluster_sync_all(); pw ^= 1;
        stage<true,  true, false>(s, pw, wid, lane, kq, rl, 3, c0, c1, h0last, h1last, hix, nullptr);
        cluster_sync_all(); pw ^= 1;
        stage<true,  false, false>(s, pw, wid, lane, kq, rl, 0, c0, c1, h0last, h1last, hix,
                                   (w < NWIN - 1) ? s.xt0[(w + 1) & 1] : nullptr);
        cluster_sync_all(); pw ^= 1;

        // ---- head: pred[b][o] = Wl[o,:]·h1[b,:] + bl[o]
        if (tid < 256) {
            int hw = tid >> 5;
            int b = hw >> 1, o = hw & 1;
            const float4* wl4 = (const float4*)&s.Wl[o * HID];
            float4 a = wl4[lane];
            const float* hb = &s.h1buf[pw][b * HB + (lane >> 3) * 36 + (lane & 7) * 4];
            float4 hh = *(const float4*)hb;
            float p = a.x * hh.x + a.y * hh.y + a.z * hh.z + a.w * hh.w;
            p += __shfl_xor_sync(0xFFFFFFFFu, p, 16);
            p += __shfl_xor_sync(0xFFFFFFFFu, p, 8);
            p += __shfl_xor_sync(0xFFFFFFFFu, p, 4);
            p += __shfl_xor_sync(0xFFFFFFFFu, p, 2);
            p += __shfl_xor_sync(0xFFFFFFFFu, p, 1);
            if (lane == 0) s.pred[b * 2 + o] = p + s.bl[o];
        }
        __syncthreads();

        // ---- bookkeeping: pred write + ring winbuf + next inputs
        const int wn = w + 1, wn2 = w + 2;
        if (tid < 64) {
            int t = tid >> 4, b = (tid >> 2) & 3, f = tid & 3;
            if (f < 3) {
                int gb = gb0 + b;
                if (t >= 1) {           // xin[t] for window w+1
                    float v;
                    if (wn < 4) {
                        if (t < 3) v = traj[(gb * TT + (wn + t)) * 3 + f];
                        else if (f == 0) v = traj[(gb * TT + (4 + wn)) * 3 + 0];
                        else v = traj[(gb * TT + 3 + w) * 3 + f] + s.pred[b * 2 + (f - 1)];
                    } else {
                        if (f < 2) {
                            if (t < 3) v = s.winbuf[(b * 4 + ((wn + t) & 3)) * 2 + f];
                            else {
                                float base = (w < 4)
                                    ? traj[(gb * TT + 3 + w) * 3 + 1 + f]
                                    : s.winbuf[(b * 4 + ((w + 3) & 3)) * 2 + f];
                                v = base + s.pred[b * 2 + f];
                            }
                        } else v = traj[(gb * TT + (wn + t)) * 3 + 0];
                    }
                    s.xin[(t * 4 + b) * 4 + f] = v;
                } else {                // xt0 for window w+2
                    float v;
                    if (wn2 < 4) {
                        v = traj[(gb * TT + wn2) * 3 + f];
                    } else {
                        if (f < 2) v = s.winbuf[(b * 4 + (wn2 & 3)) * 2 + f];
                        else v = traj[(gb * TT + wn2) * 3 + 0];
                    }
                    s.xt0[wn2 & 1][b * 4 + f] = v;
                }
            }
        } else if (tid < 72) {
            int t2 = tid - 64;
            int b = t2 >> 1, o = t2 & 1;
            int gb = gb0 + b;
            float base = (w < 4) ? traj[(gb * TT + 3 + w) * 3 + 1 + o]
                                 : s.winbuf[(b * 4 + ((w + 3) & 3)) * 2 + o];
            float pn = base + s.pred[b * 2 + o];
            s.winbuf[(b * 4 + (w & 3)) * 2 + o] = pn;
            if (rank == 0) out[(gb * NWIN + w) * 2 + o] = pn;
        }
        __syncthreads();
    }

    // ---- final hidden/cell states from acting-lane registers
    if ((lane & 7) < 2) {
        int b = lane >> 3;
        int gb = gb0 + b;
        const int OFF_H = 128 * NWIN * 2;          // 64512
        const int OFF_C = OFF_H + 2 * 128 * HID;   // 97280
        out[OFF_H + 0 * 128 * HID + gb * HID + jg] = h0last;
        out[OFF_H + 1 * 128 * HID + gb * HID + jg] = h1last;
        out[OFF_C + 0 * 128 * HID + gb * HID + jg] = c0;
        out[OFF_C + 1 * 128 * HID + gb * HID + jg] = c1;
    }
}

extern "C" void kernel_launch(void* const* d_in, const int* in_sizes, int n_in,
                              void* d_out, int out_size) {
    const float* traj = (const float*)d_in[0];
    const float* Wih0 = (const float*)d_in[1];
    const float* Whh0 = (const float*)d_in[2];
    const float* bih0 = (const float*)d_in[3];
    const float* bhh0 = (const float*)d_in[4];
    const float* Wih1 = (const float*)d_in[5];
    const float* Whh1 = (const float*)d_in[6];
    const float* bih1 = (const float*)d_in[7];
    const float* bhh1 = (const float*)d_in[8];
    const float* Wl   = (const float*)d_in[9];
    const float* bl   = (const float*)d_in[10];
    float* out = (float*)d_out;

    int smem = (int)sizeof(Smem);
    cudaFuncSetAttribute(lstm_kernel, cudaFuncAttributeMaxDynamicSharedMemorySize, smem);
    lstm_kernel<<<128, NTHREADS, smem>>>(traj, Wih0, Whh0, bih0, bhh0,
                                         Wih1, Whh1, bih1, bhh1, Wl, bl, out);
}

// round 16
// speedup vs baseline: 2.4636x; 1.0398x over previous
#include <cuda_runtime.h>
#include <cstdint>

typedef unsigned long long ull;

#define NCTA      4
#define HID       128
#define NTHREADS  512
#define NWIN      252
#define TT        256
#define PADW      132     // weight row stride (floats)
#define HB        144     // per-batch h stride: 4 chunks of (32 data + 4 pad)

// row layout: lr = w*8 + g*2 + j   (warp w owns units au=2w+j, j in {0,1})
struct Smem {
    float W1s[128 * PADW];   // Wih1
    float U1s[128 * PADW];   // Whh1
    float U0s[128 * PADW];   // Whh0
    float W0s[128 * 4];      // Wih0 (3 cols + pad)
    float b0s[128];
    float b1s[128];
    float h0buf[2][4 * HB];  // ping-pong stream buffers (cluster-shared)
    float h1buf[2][4 * HB];
    float h0t[4 * HB];       // h0'[0] of next window (written P2 tail, read P3)
    float h1t[4 * HB];       // h1'[0] of next window (written P3 tail, read P1')
    float xin[4 * 4 * 4];    // slot 0: x(w+1,0); 1: x(w+1,1); 2: x(w,2); 3: x(w,3)
    float Wl[2 * HID];
    float winbuf[4 * 4 * 2]; // ring: pred of window p at slot p&3
    float pred[4 * 2];
    float bl[2];
};

#define FFMA2(acc, w, h) \
    asm("fma.rn.f32x2 %0, %1, %2, %0;" : "+l"(acc) : "l"(w), "l"(h))

__device__ __forceinline__ float hsum2(ull a) {
    float lo, hi;
    asm("mov.b64 {%0, %1}, %2;" : "=f"(lo), "=f"(hi) : "l"(a));
    return lo + hi;
}

__device__ __forceinline__ void cluster_sync_all() {
    asm volatile("barrier.cluster.arrive.aligned;" ::: "memory");
    asm volatile("barrier.cluster.wait.aligned;" ::: "memory");
}

__device__ __forceinline__ float sigfast(float x) {
    float e = __expf(-x);
    return __fdividef(1.0f, 1.0f + e);
}
__device__ __forceinline__ float tanhfast(float x) {
    float ax = fabsf(x);
    float e = __expf(-2.0f * ax);
    float t = __fdividef(1.0f - e, 1.0f + e);
    return copysignf(t, x);
}

// chunk-padded h index: k -> (k/32)*36 + (k%32)
__device__ __forceinline__ int hIdx(int k) { return (k >> 5) * 36 + (k & 31); }

// broadcast one float to the same smem slot in all 4 cluster CTAs
__device__ __forceinline__ void push4(float v, float* dst) {
    uint32_t la = (uint32_t)__cvta_generic_to_shared(dst);
#pragma unroll
    for (int rr = 0; rr < NCTA; rr++) {
        uint32_t ra;
        asm volatile("mapa.shared::cluster.u32 %0, %1, %2;"
                     : "=r"(ra) : "r"(la), "r"(rr));
        asm volatile("st.shared::cluster.f32 [%0], %1;"
                     :: "r"(ra), "f"(v) : "memory");
    }
}

__device__ __forceinline__ float act2(float g0, float g1, float g2, float g3,
                                      float& c, bool first) {
    float ii = sigfast(g0), ff = sigfast(g1), tg = tanhfast(g2), oo = sigfast(g3);
    float cc = first ? ii * tg : fmaf(ff, c, ii * tg);
    c = cc;
    return oo * tanhfast(cc);
}

// reduce-scatter over kq (lane bits 3,4)
__device__ __forceinline__ float rscat4(const float* g, int lane) {
    const bool b4 = (lane & 16) != 0, b3 = (lane & 8) != 0;
    float s0 = b4 ? g[0] : g[2];
    float s1 = b4 ? g[1] : g[3];
    float r0 = __shfl_xor_sync(0xFFFFFFFFu, s0, 16);
    float r1 = __shfl_xor_sync(0xFFFFFFFFu, s1, 16);
    float k0 = (b4 ? g[2] : g[0]) + r0;
    float k1 = (b4 ? g[3] : g[1]) + r1;
    float s2 = b3 ? k0 : k1;
    float r2 = __shfl_xor_sync(0xFFFFFFFFu, s2, 8);
    return (b3 ? k1 : k0) + r2;
}

// Generic phase (S1/P1/P2): gates1 = Wih1·h0 (+ Whh1·h1in if HH1);
// gates0 = Whh0·h0 + Wih0·x[t_next] (if G0). Optional x0n: x-only fresh
// L0'[0] pushed into h0t.
template<bool HH1, bool G0, bool FIRST1>
__device__ __forceinline__ void stage(Smem& s, int pw, int wid, int lane,
                                      int kq, int rl, int t_next,
                                      const float* h1in, float* h1out,
                                      const float* x0n,
                                      float& c0, float& c1,
                                      float& h0last, float& h1last, int hix) {
    const int lr = wid * 8 + rl;
    const float* w1 = &s.W1s[lr * PADW + kq * 32];
    const float* u1 = &s.U1s[lr * PADW + kq * 32];
    const float* u0 = &s.U0s[lr * PADW + kq * 32];
    const float* h0 = &s.h0buf[pw][kq * 36];
    const float* h1 = HH1 ? (h1in + kq * 36) : nullptr;
    ull A1[4] = {}, A0[4] = {};
#pragma unroll
    for (int k4 = 0; k4 < 8; k4++) {
        ulonglong2 W1v = *(const ulonglong2*)(w1 + 4 * k4);
        ulonglong2 U1v, U0v;
        if (HH1) U1v = *(const ulonglong2*)(u1 + 4 * k4);
        if (G0)  U0v = *(const ulonglong2*)(u0 + 4 * k4);
#pragma unroll
        for (int b = 0; b < 4; b++) {
            ulonglong2 H0 = *(const ulonglong2*)(h0 + b * HB + 4 * k4);
            FFMA2(A1[b], W1v.x, H0.x);
            FFMA2(A1[b], W1v.y, H0.y);
            if (G0) {
                FFMA2(A0[b], U0v.x, H0.x);
                FFMA2(A0[b], U0v.y, H0.y);
            }
            if (HH1) {
                ulonglong2 H1 = *(const ulonglong2*)(h1 + b * HB + 4 * k4);
                FFMA2(A1[b], U1v.x, H1.x);
                FFMA2(A1[b], U1v.y, H1.y);
            }
        }
    }
    float g1v[4], g0v[4];
#pragma unroll
    for (int b = 0; b < 4; b++) {
        g1v[b] = hsum2(A1[b]);
        if (G0) g0v[b] = hsum2(A0[b]);
    }
    float res1 = rscat4(g1v, lane);
    float res0 = 0.0f;
    if (G0) res0 = rscat4(g0v, lane);
    float G1[4], G0g[4];
#pragma unroll
    for (int g = 0; g < 4; g++) {
        int src = (lane & 24) | (g * 2 + (lane & 1));
        G1[g] = __shfl_sync(0xFFFFFFFFu, res1, src);
        if (G0) G0g[g] = __shfl_sync(0xFFFFFFFFu, res0, src);
    }
    if ((lane & 7) < 2) {
        const int b = lane >> 3, j = lane & 1;
        const int lrb = wid * 8 + j;
        float h1n = act2(G1[0] + s.b1s[lrb + 0], G1[1] + s.b1s[lrb + 2],
                         G1[2] + s.b1s[lrb + 4], G1[3] + s.b1s[lrb + 6],
                         c1, FIRST1);
        h1last = h1n;
        push4(h1n, h1out + b * HB + hix);
        if (G0) {
            const float* x = &s.xin[(t_next * 4 + b) * 4];
            float gg[4];
#pragma unroll
            for (int g = 0; g < 4; g++) {
                int lr2 = lrb + g * 2;
                const float* wv = &s.W0s[lr2 * 4];
                gg[g] = G0g[g] + s.b0s[lr2]
                      + wv[0] * x[0] + wv[1] * x[1] + wv[2] * x[2];
            }
            float h0n = act2(gg[0], gg[1], gg[2], gg[3], c0, false);
            h0last = h0n;
            push4(h0n, &s.h0buf[pw ^ 1][b * HB + hix]);
        }
        if (x0n) {   // fresh next-window L0'[0] -> h0t
            const float* x = x0n + b * 4;
            float gg[4];
#pragma unroll
            for (int g = 0; g < 4; g++) {
                int lr2 = lrb + g * 2;
                const float* wv = &s.W0s[lr2 * 4];
                gg[g] = s.b0s[lr2]
                      + wv[0] * x[0] + wv[1] * x[1] + wv[2] * x[2];
            }
            float h0n = act2(gg[0], gg[1], gg[2], gg[3], c0, true);
            h0last = h0n;
            push4(h0n, &s.h0t[b * HB + hix]);
        }
    }
}

// P3: L1[3] (= W1·h0[3] + U1·h1[2]); if next: + L1'[0] (W1·h0t, fresh) and
// L0'[1] (U0·h0t + x(w+1,1)). Two accumulation passes keep register peak flat.
__device__ __forceinline__ void stageP3(Smem& s, int pw, int wid, int lane,
                                        int kq, int rl, bool next,
                                        float& c0, float& c1,
                                        float& h0last, float& h1last, int hix) {
    const int lr = wid * 8 + rl;
    const float* w1 = &s.W1s[lr * PADW + kq * 32];
    const float* u1 = &s.U1s[lr * PADW + kq * 32];
    const float* u0 = &s.U0s[lr * PADW + kq * 32];
    const float* h0 = &s.h0buf[pw][kq * 36];
    const float* h1 = &s.h1buf[pw][kq * 36];
    const float* ht = &s.h0t[kq * 36];
    // pass 1: A1 = W1·h0[3] + U1·h1[2]
    ull A1[4] = {};
#pragma unroll
    for (int k4 = 0; k4 < 8; k4++) {
        ulonglong2 W1v = *(const ulonglong2*)(w1 + 4 * k4);
        ulonglong2 U1v = *(const ulonglong2*)(u1 + 4 * k4);
#pragma unroll
        for (int b = 0; b < 4; b++) {
            ulonglong2 H0 = *(const ulonglong2*)(h0 + b * HB + 4 * k4);
            ulonglong2 H1 = *(const ulonglong2*)(h1 + b * HB + 4 * k4);
            FFMA2(A1[b], W1v.x, H0.x);
            FFMA2(A1[b], W1v.y, H0.y);
            FFMA2(A1[b], U1v.x, H1.x);
            FFMA2(A1[b], U1v.y, H1.y);
        }
    }
    float v1[4];
#pragma unroll
    for (int b = 0; b < 4; b++) v1[b] = hsum2(A1[b]);
    float res1 = rscat4(v1, lane);
    float G1[4];
#pragma unroll
    for (int g = 0; g < 4; g++)
        G1[g] = __shfl_sync(0xFFFFFFFFu, res1, (lane & 24) | (g * 2 + (lane & 1)));
    // pass 2 (if next): A1p = W1·h0t ; A0p = U0·h0t
    float G1p[4], G0p[4];
    if (next) {
        ull A1p[4] = {}, A0p[4] = {};
#pragma unroll
        for (int k4 = 0; k4 < 8; k4++) {
            ulonglong2 W1v = *(const ulonglong2*)(w1 + 4 * k4);
            ulonglong2 U0v = *(const ulonglong2*)(u0 + 4 * k4);
#pragma unroll
            for (int b = 0; b < 4; b++) {
                ulonglong2 HT = *(const ulonglong2*)(ht + b * HB + 4 * k4);
                FFMA2(A1p[b], W1v.x, HT.x);
                FFMA2(A1p[b], W1v.y, HT.y);
                FFMA2(A0p[b], U0v.x, HT.x);
                FFMA2(A0p[b], U0v.y, HT.y);
            }
        }
        float v1p[4], v0p[4];
#pragma unroll
        for (int b = 0; b < 4; b++) {
            v1p[b] = hsum2(A1p[b]);
            v0p[b] = hsum2(A0p[b]);
        }
        float r1p = rscat4(v1p, lane);
        float r0p = rscat4(v0p, lane);
#pragma unroll
        for (int g = 0; g < 4; g++) {
            int src = (lane & 24) | (g * 2 + (lane & 1));
            G1p[g] = __shfl_sync(0xFFFFFFFFu, r1p, src);
            G0p[g] = __shfl_sync(0xFFFFFFFFu, r0p, src);
        }
    }
    if ((lane & 7) < 2) {
        const int b = lane >> 3, j = lane & 1;
        const int lrb = wid * 8 + j;
        float h1n = act2(G1[0] + s.b1s[lrb + 0], G1[1] + s.b1s[lrb + 2],
                         G1[2] + s.b1s[lrb + 4], G1[3] + s.b1s[lrb + 6],
                         c1, false);
        h1last = h1n;
        push4(h1n, &s.h1buf[pw ^ 1][b * HB + hix]);
        if (next) {
            float h1p = act2(G1p[0] + s.b1s[lrb + 0], G1p[1] + s.b1s[lrb + 2],
                             G1p[2] + s.b1s[lrb + 4], G1p[3] + s.b1s[lrb + 6],
                             c1, true);
            push4(h1p, &s.h1t[b * HB + hix]);
            const float* x = &s.xin[(1 * 4 + b) * 4];
            float gg[4];
#pragma unroll
            for (int g = 0; g < 4; g++) {
                int lr2 = lrb + g * 2;
                const float* wv = &s.W0s[lr2 * 4];
                gg[g] = G0p[g] + s.b0s[lr2]
                      + wv[0] * x[0] + wv[1] * x[1] + wv[2] * x[2];
            }
            float h0n = act2(gg[0], gg[1], gg[2], gg[3], c0, false);
            h0last = h0n;
            push4(h0n, &s.h0buf[pw ^ 1][b * HB + hix]);
        }
    }
}

extern __shared__ float smem_raw[];

__global__ void __cluster_dims__(NCTA, 1, 1) __launch_bounds__(NTHREADS, 1)
lstm_kernel(const float* __restrict__ traj,
            const float* __restrict__ Wih0, const float* __restrict__ Whh0,
            const float* __restrict__ bih0, const float* __restrict__ bhh0,
            const float* __restrict__ Wih1, const float* __restrict__ Whh1,
            const float* __restrict__ bih1, const float* __restrict__ bhh1,
            const float* __restrict__ Wl,   const float* __restrict__ bl,
            float* __restrict__ out) {
    Smem& s = *reinterpret_cast<Smem*>(smem_raw);
    const int tid = threadIdx.x;
    uint32_t rank;
    asm("mov.u32 %0, %%cluster_ctarank;" : "=r"(rank));
    const int cluster = blockIdx.x / NCTA;
    const int gb0 = cluster * 4;

    // ---- weights: local row lr = w*8 + g*2 + j  <->  global gr = g*128 + rank*32 + 2w+j
    for (int i = tid; i < 128 * HID; i += NTHREADS) {
        int lr = i / HID, k = i % HID;
        int wv = lr >> 3, rl = lr & 7, g = rl >> 1, j = rl & 1;
        int gr = g * 128 + (int)rank * 32 + 2 * wv + j;
        s.W1s[lr * PADW + k] = Wih1[gr * HID + k];
        s.U1s[lr * PADW + k] = Whh1[gr * HID + k];
        s.U0s[lr * PADW + k] = Whh0[gr * HID + k];
    }
    for (int lr = tid; lr < 128; lr += NTHREADS) {
        int wv = lr >> 3, rl = lr & 7, g = rl >> 1, j = rl & 1;
        int gr = g * 128 + (int)rank * 32 + 2 * wv + j;
        s.W0s[lr * 4 + 0] = Wih0[gr * 3 + 0];
        s.W0s[lr * 4 + 1] = Wih0[gr * 3 + 1];
        s.W0s[lr * 4 + 2] = Wih0[gr * 3 + 2];
        s.W0s[lr * 4 + 3] = 0.0f;
        s.b0s[lr] = bih0[gr] + bhh0[gr];
        s.b1s[lr] = bih1[gr] + bhh1[gr];
    }
    for (int i = tid; i < 2 * HID; i += NTHREADS) s.Wl[i] = Wl[i];
    if (tid < 2) s.bl[tid] = bl[tid];

    // ---- prologue inputs: xin[t] = raw traj rows 0..3 (window 0)
    if (tid < 64) {
        int t = tid >> 4, b = (tid >> 2) & 3, f = tid & 3;
        if (f < 3)
            s.xin[(t * 4 + b) * 4 + f] = traj[((gb0 + b) * TT + t) * 3 + f];
    }
    __syncthreads();

    const int wid  = tid >> 5;
    const int lane = tid & 31;
    const int kq   = lane >> 3;
    const int rl   = lane & 7;
    const int au  = 2 * wid + (lane & 1);
    const int jg  = (int)rank * 32 + au;
    const int hix = hIdx(jg);

    int pw = 0;
    float c0 = 0.f, c1 = 0.f, h0last = 0.f, h1last = 0.f;

    // ---- prologue s0: L0[0] of window 0 (x-only, fresh)
    if ((lane & 7) < 2) {
        int b = lane >> 3, j = lane & 1;
        const float* x = &s.xin[(0 * 4 + b) * 4];
        float g4[4];
#pragma unroll
        for (int g = 0; g < 4; g++) {
            int lr = wid * 8 + g * 2 + j;
            const float* wv = &s.W0s[lr * 4];
            g4[g] = s.b0s[lr] + wv[0] * x[0] + wv[1] * x[1] + wv[2] * x[2];
        }
        float h0n = act2(g4[0], g4[1], g4[2], g4[3], c0, true);
        h0last = h0n;
        push4(h0n, &s.h0buf[pw ^ 1][b * HB + hix]);
    }
    cluster_sync_all();
    pw ^= 1;

    // ---- prologue S1: L1[0] (fresh, -> h1t) + L0[1]
    stage<false, true, true>(s, pw, wid, lane, kq, rl, 1, nullptr, s.h1t,
                             nullptr, c0, c1, h0last, h1last, hix);
    cluster_sync_all();
    pw ^= 1;

    // ---- rebuild xin[0] = x(1,0) = traj row 1, xin[1] = x(1,1) = traj row 2
    if (tid < 32) {
        int t = tid >> 4, b = (tid >> 2) & 3, f = tid & 3;
        if (f < 3)
            s.xin[(t * 4 + b) * 4 + f] = traj[((gb0 + b) * TT + 1 + t) * 3 + f];
    }
    __syncthreads();

#pragma unroll 1
    for (int w = 0; w < NWIN; w++) {
        const bool next = (w < NWIN - 1);
        // P1: L1[1] (h1 from h1t) + L0[2]
        stage<true, true, false>(s, pw, wid, lane, kq, rl, 2,
                                 s.h1t, s.h1buf[pw ^ 1], nullptr,
                                 c0, c1, h0last, h1last, hix);
        cluster_sync_all(); pw ^= 1;
        // P2: L1[2] + L0[3]; tail: L0'[0] -> h0t (if next)
        stage<true, true, false>(s, pw, wid, lane, kq, rl, 3,
                                 s.h1buf[pw], s.h1buf[pw ^ 1],
                                 next ? s.xin : nullptr,
                                 c0, c1, h0last, h1last, hix);
        cluster_sync_all(); pw ^= 1;
        // P3: L1[3] + (if next) L1'[0] -> h1t, L0'[1] -> h0buf
        stageP3(s, pw, wid, lane, kq, rl, next, c0, c1, h0last, h1last, hix);
        cluster_sync_all(); pw ^= 1;

        // ---- head: pred[b][o] = Wl[o,:]·h1[3] + bl[o]
        if (tid < 256) {
            int hw = tid >> 5;
            int b = hw >> 1, o = hw & 1;
            const float4* wl4 = (const float4*)&s.Wl[o * HID];
            float4 a = wl4[lane];
            const float* hb = &s.h1buf[pw][b * HB + (lane >> 3) * 36 + (lane & 7) * 4];
            float4 hh = *(const float4*)hb;
            float p = a.x * hh.x + a.y * hh.y + a.z * hh.z + a.w * hh.w;
            p += __shfl_xor_sync(0xFFFFFFFFu, p, 16);
            p += __shfl_xor_sync(0xFFFFFFFFu, p, 8);
            p += __shfl_xor_sync(0xFFFFFFFFu, p, 4);
            p += __shfl_xor_sync(0xFFFFFFFFu, p, 2);
            p += __shfl_xor_sync(0xFFFFFFFFu, p, 1);
            if (lane == 0) s.pred[b * 2 + o] = p + s.bl[o];
        }
        __syncthreads();

        // ---- bookkeeping: pred/winbuf/out + next input slots
        const int wn = w + 1, wn2 = w + 2;
        if (tid < 64) {
            int t = tid >> 4, b = (tid >> 2) & 3, f = tid & 3;
            if (f < 3) {
                int gb = gb0 + b;
                float v;
                if (t == 0) {            // x(w+2, 0)
                    if (wn2 < 4) v = traj[(gb * TT + wn2) * 3 + f];
                    else v = (f < 2) ? s.winbuf[(b * 4 + (wn2 & 3)) * 2 + f]
                                     : traj[(gb * TT + wn2) * 3 + 0];
                } else if (t == 1) {     // x(w+2, 1)
                    if (wn2 < 4) v = traj[(gb * TT + wn2 + 1) * 3 + f];
                    else v = (f < 2) ? s.winbuf[(b * 4 + ((wn2 + 1) & 3)) * 2 + f]
                                     : traj[(gb * TT + wn2 + 1) * 3 + 0];
                } else if (t == 2) {     // x(w+1, 2)
                    if (wn < 4) v = traj[(gb * TT + wn + 2) * 3 + f];
                    else v = (f < 2) ? s.winbuf[(b * 4 + ((wn + 2) & 3)) * 2 + f]
                                     : traj[(gb * TT + wn + 2) * 3 + 0];
                } else {                 // x(w+1, 3)
                    if (wn < 4) {
                        if (f == 0) v = traj[(gb * TT + 4 + wn) * 3 + 0];
                        else v = traj[(gb * TT + 3 + w) * 3 + f] + s.pred[b * 2 + (f - 1)];
                    } else {
                        if (f < 2) {
                            float base = (w < 4)
                                ? traj[(gb * TT + 3 + w) * 3 + 1 + f]
                                : s.winbuf[(b * 4 + ((w + 3) & 3)) * 2 + f];
                            v = base + s.pred[b * 2 + f];
                        } else v = traj[(gb * TT + wn + 3) * 3 + 0];
                    }
                }
                s.xin[(t * 4 + b) * 4 + f] = v;
            }
        } else if (tid < 72) {
            int t2 = tid - 64;
            int b = t2 >> 1, o = t2 & 1;
            int gb = gb0 + b;
            float base = (w < 4) ? traj[(gb * TT + 3 + w) * 3 + 1 + o]
                                 : s.winbuf[(b * 4 + ((w + 3) & 3)) * 2 + o];
            float pn = base + s.pred[b * 2 + o];
            s.winbuf[(b * 4 + (w & 3)) * 2 + o] = pn;
            if (rank == 0) out[(gb * NWIN + w) * 2 + o] = pn;
        }
        __syncthreads();
    }

    // ---- final hidden/cell states from acting-lane registers
    if ((lane & 7) < 2) {
        int b = lane >> 3;
        int gb = gb0 + b;
        const int OFF_H = 128 * NWIN * 2;          // 64512
        const int OFF_C = OFF_H + 2 * 128 * HID;   // 97280
        out[OFF_H + 0 * 128 * HID + gb * HID + jg] = h0last;
        out[OFF_H + 1 * 128 * HID + gb * HID + jg] = h1last;
        out[OFF_C + 0 * 128 * HID + gb * HID + jg] = c0;
        out[OFF_C + 1 * 128 * HID + gb * HID + jg] = c1;
    }
}

extern "C" void kernel_launch(void* const* d_in, const int* in_sizes, int n_in,
                              void* d_out, int out_size) {
    const float* traj = (const float*)d_in[0];
    const float* Wih0 = (const float*)d_in[1];
    const float* Whh0 = (const float*)d_in[2];
    const float* bih0 = (const float*)d_in[3];
    const float* bhh0 = (const float*)d_in[4];
    const float* Wih1 = (const float*)d_in[5];
    const float* Whh1 = (const float*)d_in[6];
    const float* bih1 = (const float*)d_in[7];
    const float* bhh1 = (const float*)d_in[8];
    const float* Wl   = (const float*)d_in[9];
    const float* bl   = (const float*)d_in[10];
    float* out = (float*)d_out;

    int smem = (int)sizeof(Smem);
    cudaFuncSetAttribute(lstm_kernel, cudaFuncAttributeMaxDynamicSharedMemorySize, smem);
    lstm_kernel<<<128, NTHREADS, smem>>>(traj, Wih0, Whh0, bih0, bhh0,
                                         Wih1, Whh1, bih1, bhh1, Wl, bl, out);
}